// round 1
// baseline (speedup 1.0000x reference)
#include <cuda_runtime.h>
#include <math.h>
#include <stdint.h>

// ---------------------------------------------------------------------------
// Sizes: B=8, C=64, H=W=64 (after pool), L=4096, DI=128, DS=16
// All activation tensors live channel-major: [b][ch][l], l = y*64+x.
// ---------------------------------------------------------------------------

#define O_POOLED   0u            // 8*3*4096            = 98304
#define O_RAW1     98304u        // 8*64*4096           = 2097152
#define O_RAW2     2195456u
#define O_X3       4292608u
#define O_RAW3     6389760u
#define O_XZ       8486912u      // 8*256*4096          = 8388608
#define O_XSC      16875520u     // 8*128*4096          = 4194304
#define O_DBL      21069824u     // 8*36*4096           = 1179648
#define O_DT       22249472u     // 4194304
#define O_Y        26443776u     // 4194304
#define O_GATED    30638080u     // 4194304
#define O_X4       34832384u     // 2097152
#define O_RAW4     36929536u     // 2097152
#define O_W1T      39026688u     // 147*64 = 9408
#define O_W2T      39036096u     // 576*64 = 36864
#define O_W3T      39072960u     // 4096
#define O_W4T      39077056u     // 4096
#define O_INPT     39081152u     // 64*256 = 16384
#define O_XPT      39097536u     // 128*36 = 4608
#define O_OPT      39102144u     // 128*64 = 8192
#define O_A2       39110336u     // 2048
#define O_SB1      39112384u     // 128 each (scale[64], bias[64])
#define O_SB2      39112512u
#define O_SB3      39112640u
#define O_SB4      39112768u
#define SCRATCH_SIZE 39112896u

__device__ float g_scratch[SCRATCH_SIZE];

__device__ __forceinline__ float ex2f(float x) {
    float r; asm("ex2.approx.ftz.f32 %0, %1;" : "=f"(r) : "f"(x)); return r;
}
__device__ __forceinline__ float siluf(float x) {
    return x / (1.0f + expf(-x));
}
__device__ __forceinline__ float softplusf(float x) {
    if (x > 20.0f) return x;
    if (x < -20.0f) return expf(x);
    return log1pf(expf(x));
}

// ---------------------------------------------------------------------------
// Prep: transpose all weight matrices to [k][n] layout, fold log2(e) into A.
// ---------------------------------------------------------------------------
__global__ void prep_kernel(float* S,
    const float* __restrict__ w1, const float* __restrict__ w2,
    const float* __restrict__ w3, const float* __restrict__ w4,
    const float* __restrict__ inp, const float* __restrict__ xp,
    const float* __restrict__ op, const float* __restrict__ alog)
{
    int i = blockIdx.x * 256 + threadIdx.x;
    if (i < 9408) { int k = i >> 6, co = i & 63; S[O_W1T + i] = w1[co * 147 + k]; return; }
    i -= 9408;
    if (i < 36864) { int k = i >> 6, co = i & 63; S[O_W2T + i] = w2[co * 576 + k]; return; }
    i -= 36864;
    if (i < 4096) { int k = i >> 6, co = i & 63; S[O_W3T + i] = w3[co * 64 + k]; return; }
    i -= 4096;
    if (i < 4096) { int k = i >> 6, co = i & 63; S[O_W4T + i] = w4[co * 64 + k]; return; }
    i -= 4096;
    if (i < 16384) { int c = i >> 8, j = i & 255; S[O_INPT + i] = inp[j * 64 + c]; return; }
    i -= 16384;
    if (i < 4608) { int d = i / 36, j = i - d * 36; S[O_XPT + i] = xp[j * 128 + d]; return; }
    i -= 4608;
    if (i < 8192) { int d = i >> 6, c = i & 63; S[O_OPT + i] = op[c * 128 + d]; return; }
    i -= 8192;
    if (i < 2048) { S[O_A2 + i] = -expf(alog[i]) * 1.4426950408889634f; return; }
}

// ---------------------------------------------------------------------------
// 2x2 maxpool: (8,3,128,128) -> (8,3,64,64)
// ---------------------------------------------------------------------------
__global__ void pool_kernel(float* S, const float* __restrict__ x)
{
    int i = blockIdx.x * 256 + threadIdx.x;
    if (i >= 98304) return;
    int bc = i >> 12;          // b*3+c
    int p  = i & 4095;
    int y = p >> 6, xx = p & 63;
    const float* src = x + (size_t)bc * 16384 + (y * 2) * 128 + xx * 2;
    float v = fmaxf(fmaxf(src[0], src[1]), fmaxf(src[128], src[129]));
    S[O_POOLED + i] = v;
}

// ---------------------------------------------------------------------------
// Unified implicit-GEMM:  C[(b,l), n] = sum_k A'[(b,l), k] * Bt[k][n]
//   A layout [b][Cin][4096]; KS in {1,3,7} selects im2col addressing.
//   AFF: apply per-input-channel affine+relu (BN normalize of previous stage).
//   RES: add residual (same layout as output).
// Block: 64 (m=l) x 64 (n) tile, 256 threads, 4x4 per-thread register tile.
// Grid: x = 512 (8 batches * 64 l-tiles of 64), y = ceil(N/64).
// ---------------------------------------------------------------------------
template<int KS, bool AFF, bool RES>
__global__ void __launch_bounds__(256) gemm_kernel(
    const float* __restrict__ A, const float* __restrict__ Bt,
    float* __restrict__ Cout, const float* __restrict__ sb,
    const float* __restrict__ Res, int Cin, int K, int N, int ldb)
{
    __shared__ __align__(16) float As[16][64];
    __shared__ __align__(16) float Bs[16][64];
    int tid = threadIdx.x;
    int tm = tid & 15, tn = tid >> 4;
    int bb = blockIdx.x >> 6;
    int l0 = (blockIdx.x & 63) << 6;
    int n0 = blockIdx.y << 6;
    float acc[4][4];
    #pragma unroll
    for (int i = 0; i < 4; i++)
        #pragma unroll
        for (int j = 0; j < 4; j++) acc[i][j] = 0.0f;

    int nch = (K + 15) >> 4;
    for (int kc = 0; kc < nch; kc++) {
        int k0 = kc << 4;
        #pragma unroll
        for (int i = 0; i < 4; i++) {
            int lin = i * 256 + tid;
            int kk = lin >> 6, m = lin & 63;
            int k = k0 + kk;
            float v = 0.0f;
            if (k < K) {
                int ci, dy, dx;
                if (KS == 1)      { ci = k;      dy = 0; dx = 0; }
                else if (KS == 3) { ci = k / 9;  int r = k - ci * 9;  dy = r / 3 - 1; dx = r - (r / 3) * 3 - 1; }
                else              { ci = k / 49; int r = k - ci * 49; dy = r / 7 - 3; dx = r - (r / 7) * 7 - 3; }
                int l = l0 + m;
                int y = (l >> 6) + dy, x = (l & 63) + dx;
                bool ok = (KS == 1) || ((unsigned)y < 64u && (unsigned)x < 64u);
                if (ok) {
                    size_t addr = ((size_t)(bb * Cin + ci) << 12) + (KS == 1 ? l : (y * 64 + x));
                    float raw = A[addr];
                    v = AFF ? fmaxf(0.0f, fmaf(sb[ci], raw, sb[64 + ci])) : raw;
                }
            }
            As[kk][m] = v;
        }
        #pragma unroll
        for (int i = 0; i < 4; i++) {
            int lin = i * 256 + tid;
            int kk = lin >> 6, n = lin & 63;
            int k = k0 + kk, gn = n0 + n;
            Bs[kk][n] = (k < K && gn < N) ? Bt[k * ldb + gn] : 0.0f;
        }
        __syncthreads();
        #pragma unroll
        for (int kk = 0; kk < 16; kk++) {
            float4 a4 = *(const float4*)&As[kk][tm << 2];
            float4 b4 = *(const float4*)&Bs[kk][tn << 2];
            float a[4] = {a4.x, a4.y, a4.z, a4.w};
            float b[4] = {b4.x, b4.y, b4.z, b4.w};
            #pragma unroll
            for (int i = 0; i < 4; i++)
                #pragma unroll
                for (int j = 0; j < 4; j++)
                    acc[i][j] = fmaf(a[i], b[j], acc[i][j]);
        }
        __syncthreads();
    }
    #pragma unroll
    for (int j = 0; j < 4; j++) {
        int gn = n0 + (tn << 2) + j;
        if (gn < N) {
            size_t base = ((size_t)(bb * N + gn) << 12) + l0 + (tm << 2);
            float4 v = make_float4(acc[0][j], acc[1][j], acc[2][j], acc[3][j]);
            if (RES) {
                float4 r = *(const float4*)&Res[base];
                v.x += r.x; v.y += r.y; v.z += r.z; v.w += r.w;
            }
            *(float4*)&Cout[base] = v;
        }
    }
}

// ---------------------------------------------------------------------------
// BN stats: per-channel mean/var over (b, l); emits scale=g*rsqrt(var+eps),
// bias = b - mu*scale.   64 blocks (one per channel).
// ---------------------------------------------------------------------------
__global__ void bnstats_kernel(const float* __restrict__ raw, float* sb,
                               const float* __restrict__ g, const float* __restrict__ bta)
{
    int c = blockIdx.x, tid = threadIdx.x;
    double s = 0.0, s2 = 0.0;
    const float* p = raw + ((size_t)c << 12);
    for (int j = tid; j < 32768; j += 256) {
        int b = j >> 12, l = j & 4095;
        float v = p[((size_t)b << 18) + l];
        s += v; s2 += (double)v * v;
    }
    __shared__ double sh[256], sh2[256];
    sh[tid] = s; sh2[tid] = s2;
    __syncthreads();
    for (int o = 128; o > 0; o >>= 1) {
        if (tid < o) { sh[tid] += sh[tid + o]; sh2[tid] += sh2[tid + o]; }
        __syncthreads();
    }
    if (tid == 0) {
        double mu = sh[0] / 32768.0;
        double var = sh2[0] / 32768.0 - mu * mu;
        float sc = g[c] * rsqrtf((float)var + 1e-5f);
        sb[c] = sc;
        sb[64 + c] = bta[c] - (float)mu * sc;
    }
}

// elementwise normalize+relu (materializes x3)
__global__ void norm_kernel(const float* __restrict__ raw, float* __restrict__ out,
                            const float* __restrict__ sb)
{
    int i = blockIdx.x * 256 + threadIdx.x;     // float4 index, 524288 total
    if (i >= 524288) return;
    int c = (i >> 10) & 63;
    float s = sb[c], t = sb[64 + c];
    float4 v = ((const float4*)raw)[i];
    v.x = fmaxf(0.0f, fmaf(s, v.x, t));
    v.y = fmaxf(0.0f, fmaf(s, v.y, t));
    v.z = fmaxf(0.0f, fmaf(s, v.z, t));
    v.w = fmaxf(0.0f, fmaf(s, v.w, t));
    ((float4*)out)[i] = v;
}

// ---------------------------------------------------------------------------
// depthwise causal conv1d (k=4) + bias + silu:  xz[b][d][l] -> xsc[b][d][l]
// ---------------------------------------------------------------------------
__global__ void dwconv_kernel(const float* __restrict__ xz, float* __restrict__ xsc,
                              const float* __restrict__ cw, const float* __restrict__ cb)
{
    int idx = blockIdx.x * 256 + threadIdx.x;   // 1048576, 4 l each
    if (idx >= 1048576) return;
    int b = idx >> 17;
    int r = idx & 131071;
    int d = r >> 10;
    int l0 = (r & 1023) << 2;
    const float* in = xz + ((size_t)(b * 256 + d) << 12);
    float* out = xsc + ((size_t)(b * 128 + d) << 12) + l0;
    float w0 = cw[d * 4], w1 = cw[d * 4 + 1], w2 = cw[d * 4 + 2], w3 = cw[d * 4 + 3];
    float bias = cb[d];
    #pragma unroll
    for (int u = 0; u < 4; u++) {
        int l = l0 + u;
        float a = fmaf(in[l], w3, bias);
        if (l >= 1) a = fmaf(in[l - 1], w2, a);
        if (l >= 2) a = fmaf(in[l - 2], w1, a);
        if (l >= 3) a = fmaf(in[l - 3], w0, a);
        out[u] = siluf(a);
    }
}

// ---------------------------------------------------------------------------
// dt = softplus(dbl[:, :4] @ dt_w.T + dt_b), layout [b][d][t]
// ---------------------------------------------------------------------------
__global__ void dt_kernel(const float* __restrict__ dbl, float* __restrict__ dt,
                          const float* __restrict__ dtw, const float* __restrict__ dtb)
{
    int idx = blockIdx.x * 256 + threadIdx.x;   // 4194304
    if (idx >= 4194304) return;
    int b = idx >> 19;
    int r = idx & 524287;
    int d = r >> 12;
    int t = r & 4095;
    const float* db = dbl + ((size_t)(b * 36) << 12) + t;
    float acc = dtb[d];
    acc = fmaf(db[0],         dtw[d * 4 + 0], acc);
    acc = fmaf(db[4096],      dtw[d * 4 + 1], acc);
    acc = fmaf(db[8192],      dtw[d * 4 + 2], acc);
    acc = fmaf(db[12288],     dtw[d * 4 + 3], acc);
    dt[idx] = softplusf(acc);
}

// ---------------------------------------------------------------------------
// Selective scan. One warp handles (b, d-pair); lane = state s (16 per half).
// h_{t} = exp2(dt*A2[d,s]) * h_{t-1} + dt*x*B[t,s];  y[t] = sum_s h*C[t,s]
// ---------------------------------------------------------------------------
__global__ void scan_kernel(const float* __restrict__ dt, const float* __restrict__ xs,
                            const float* __restrict__ dbl, const float* __restrict__ A2,
                            float* __restrict__ yb)
{
    int wid = blockIdx.x;          // 512
    int lane = threadIdx.x;        // 32
    int b = wid >> 6;
    int dp = wid & 63;
    int half = lane >> 4, s = lane & 15;
    int d = dp * 2 + half;
    const float* dtp = dt + ((size_t)(b * 128 + d) << 12);
    const float* xp  = xs + ((size_t)(b * 128 + d) << 12);
    const float* Bp  = dbl + ((size_t)(b * 36 + 4 + s) << 12);
    const float* Cp  = dbl + ((size_t)(b * 36 + 20 + s) << 12);
    float* yo = yb + ((size_t)(b * 128 + d) << 12);
    float Av = A2[d * 16 + s];
    float h = 0.0f;
    for (int t = 0; t < 4096; t += 4) {
        float4 B4 = *(const float4*)(Bp + t);
        float4 C4 = *(const float4*)(Cp + t);
        float4 D4 = *(const float4*)(dtp + t);
        float4 X4 = *(const float4*)(xp + t);
        float Ba[4] = {B4.x, B4.y, B4.z, B4.w};
        float Ca[4] = {C4.x, C4.y, C4.z, C4.w};
        float Da[4] = {D4.x, D4.y, D4.z, D4.w};
        float Xa[4] = {X4.x, X4.y, X4.z, X4.w};
        float ya[4];
        #pragma unroll
        for (int u = 0; u < 4; u++) {
            float a = ex2f(Da[u] * Av);
            h = fmaf(a, h, Da[u] * Xa[u] * Ba[u]);
            float v = h * Ca[u];
            v += __shfl_xor_sync(0xffffffffu, v, 1);
            v += __shfl_xor_sync(0xffffffffu, v, 2);
            v += __shfl_xor_sync(0xffffffffu, v, 4);
            v += __shfl_xor_sync(0xffffffffu, v, 8);
            ya[u] = v;
        }
        if (s == 0) *(float4*)(yo + t) = make_float4(ya[0], ya[1], ya[2], ya[3]);
    }
}

// ---------------------------------------------------------------------------
// gated = (y + D[d]*xs) * silu(z)
// ---------------------------------------------------------------------------
__global__ void gate_kernel(const float* __restrict__ yb, const float* __restrict__ xs,
                            const float* __restrict__ xz, const float* __restrict__ Dp,
                            float* __restrict__ gated)
{
    int idx = blockIdx.x * 256 + threadIdx.x;   // 1048576 float4s
    if (idx >= 1048576) return;
    int b = idx >> 17;
    int r = idx & 131071;
    int d = r >> 10;
    int tq = (r & 1023) << 2;
    float4 y4 = ((const float4*)yb)[idx];
    float4 x4 = ((const float4*)xs)[idx];
    float4 z4 = *(const float4*)(xz + ((size_t)(b * 256 + 128 + d) << 12) + tq);
    float Dd = Dp[d];
    float4 o;
    o.x = fmaf(Dd, x4.x, y4.x) * siluf(z4.x);
    o.y = fmaf(Dd, x4.y, y4.y) * siluf(z4.y);
    o.z = fmaf(Dd, x4.z, y4.z) * siluf(z4.z);
    o.w = fmaf(Dd, x4.w, y4.w) * siluf(z4.w);
    ((float4*)gated)[idx] = o;
}

// ---------------------------------------------------------------------------
// finalize: out[0:2097152] = relu(bn4(raw4)); p1/p2 fills (analytically const:
// LayerNorm over a singleton channel axis collapses to the LN bias).
// ---------------------------------------------------------------------------
__global__ void finalize_kernel(const float* __restrict__ raw4, const float* __restrict__ sb,
                                const float* __restrict__ lnb1, const float* __restrict__ lnb2,
                                float* __restrict__ out, int out_size)
{
    int i = blockIdx.x * 256 + threadIdx.x;
    if (i >= out_size) return;
    if (i < 2097152) {
        int c = (i >> 12) & 63;
        out[i] = fmaxf(0.0f, fmaf(sb[c], raw4[i], sb[64 + c]));
    } else if (i < 2097152 + 32768) {
        out[i] = lnb1[0];
    } else {
        out[i] = lnb2[0];
    }
}

// ---------------------------------------------------------------------------
extern "C" void kernel_launch(void* const* d_in, const int* in_sizes, int n_in,
                              void* d_out, int out_size)
{
    float* S = nullptr;
    cudaGetSymbolAddress((void**)&S, g_scratch);

    const float* x       = (const float*)d_in[0];
    const float* w1      = (const float*)d_in[1];
    const float* g1      = (const float*)d_in[2];
    const float* b1      = (const float*)d_in[3];
    const float* w2      = (const float*)d_in[4];
    const float* g2      = (const float*)d_in[5];
    const float* b2      = (const float*)d_in[6];
    const float* w3      = (const float*)d_in[7];
    const float* g3      = (const float*)d_in[8];
    const float* b3      = (const float*)d_in[9];
    const float* w4      = (const float*)d_in[10];
    const float* g4      = (const float*)d_in[11];
    const float* b4      = (const float*)d_in[12];
    const float* lnb1    = (const float*)d_in[15];
    const float* lnb2    = (const float*)d_in[18];
    const float* in_proj = (const float*)d_in[19];
    const float* conv_w  = (const float*)d_in[20];
    const float* conv_b  = (const float*)d_in[21];
    const float* x_proj  = (const float*)d_in[22];
    const float* dt_w    = (const float*)d_in[23];
    const float* dt_b    = (const float*)d_in[24];
    const float* A_log   = (const float*)d_in[25];
    const float* Dp      = (const float*)d_in[26];
    const float* out_proj= (const float*)d_in[27];
    float* out = (float*)d_out;

    prep_kernel<<<336, 256>>>(S, w1, w2, w3, w4, in_proj, x_proj, out_proj, A_log);
    pool_kernel<<<384, 256>>>(S, x);

    // conv1 7x7 (Cin=3, K=147)
    gemm_kernel<7, false, false><<<dim3(512, 1), 256>>>(S + O_POOLED, S + O_W1T, S + O_RAW1,
                                                        nullptr, nullptr, 3, 147, 64, 64);
    bnstats_kernel<<<64, 256>>>(S + O_RAW1, S + O_SB1, g1, b1);

    // conv2 3x3 (K=576), input = bn1+relu applied on the fly
    gemm_kernel<3, true, false><<<dim3(512, 1), 256>>>(S + O_RAW1, S + O_W2T, S + O_RAW2,
                                                       S + O_SB1, nullptr, 64, 576, 64, 64);
    bnstats_kernel<<<64, 256>>>(S + O_RAW2, S + O_SB2, g2, b2);

    // conv3 1x1
    gemm_kernel<1, true, false><<<dim3(512, 1), 256>>>(S + O_RAW2, S + O_W3T, S + O_RAW3,
                                                       S + O_SB2, nullptr, 64, 64, 64, 64);
    bnstats_kernel<<<64, 256>>>(S + O_RAW3, S + O_SB3, g3, b3);
    norm_kernel<<<2048, 256>>>(S + O_RAW3, S + O_X3, S + O_SB3);

    // mamba: in_proj (N=256)
    gemm_kernel<1, false, false><<<dim3(512, 4), 256>>>(S + O_X3, S + O_INPT, S + O_XZ,
                                                        nullptr, nullptr, 64, 64, 256, 256);
    dwconv_kernel<<<4096, 256>>>(S + O_XZ, S + O_XSC, conv_w, conv_b);

    // x_proj (N=36)
    gemm_kernel<1, false, false><<<dim3(512, 1), 256>>>(S + O_XSC, S + O_XPT, S + O_DBL,
                                                        nullptr, nullptr, 128, 128, 36, 36);
    dt_kernel<<<16384, 256>>>(S + O_DBL, S + O_DT, dt_w, dt_b);
    scan_kernel<<<512, 32>>>(S + O_DT, S + O_XSC, S + O_DBL, S + O_A2, S + O_Y);
    gate_kernel<<<4096, 256>>>(S + O_Y, S + O_XSC, S + O_XZ, Dp, S + O_GATED);

    // out_proj + residual add of x3
    gemm_kernel<1, false, true><<<dim3(512, 1), 256>>>(S + O_GATED, S + O_OPT, S + O_X4,
                                                       nullptr, S + O_X3, 128, 128, 64, 64);

    // conv4 1x1 (input = x4, no affine)
    gemm_kernel<1, false, false><<<dim3(512, 1), 256>>>(S + O_X4, S + O_W4T, S + O_RAW4,
                                                        nullptr, nullptr, 64, 64, 64, 64);
    bnstats_kernel<<<64, 256>>>(S + O_RAW4, S + O_SB4, g4, b4);

    finalize_kernel<<<(out_size + 255) / 256, 256>>>(S + O_RAW4, S + O_SB4, lnb1, lnb2,
                                                     out, out_size);
}